// round 13
// baseline (speedup 1.0000x reference)
#include <cuda_runtime.h>
#include <stdint.h>

// weights[T=8] f32; bond_src/dst/type [B=1024,E=512] i32 (+1 node offset);
// out [B,256,256] f32 (256 MiB).
//
// Fused single-pass kernel: per-batch smem hash dedup (reference
// last-write-wins order), bitmap + rank/popcount + compact values,
// ONE streaming pass writing every 128B line exactly once.
//
// R13 delta: 512 blocks x 2 batches each -> grid (512) < concurrent CTA slots
// (148 SM x 4 occ = 592) -> SINGLE wave. Removes the wave transition and the
// second wave's exposed prologue; batch-1 prologue hides behind the chip-wide
// store stream. Everything else is the proven R12 structure (47.7us).
static constexpr int Bb      = 1024;
static constexpr int BATCHES_PER_BLOCK = 2;
static constexpr int GRID    = Bb / BATCHES_PER_BLOCK;   // 512 blocks, 1 wave
static constexpr int E       = 512;
static constexpr int Nn      = 256;
static constexpr int CELLS   = Nn * Nn;     // 65536 cells / batch (256 KB)
static constexpr int NWORDS  = CELLS / 32;  // 2048 bitmap words
static constexpr int TS      = 2048;        // hash slots (<=0.5 load)
static constexpr int THREADS = 512;
static constexpr int ITERS   = (CELLS / 4) / THREADS;   // 32 float4 per thread

__device__ __forceinline__ uint32_t ht_hash(uint32_t key) {
    return (key * 2654435761u) >> (32 - 11);            // -> [0, 2048)
}

// Entry: key(16b hi) | prio(16b lo). key in [257,65535] so entry!=0 when valid.
// Returns the slot where `key` resides.
__device__ __forceinline__ uint32_t ht_insert(uint32_t* table, uint32_t key, uint32_t prio) {
    uint32_t entry = (key << 16) | prio;
    uint32_t h = ht_hash(key);
    #pragma unroll 1
    while (true) {
        uint32_t cur = table[h];
        if (cur == 0u) {
            uint32_t old = atomicCAS(&table[h], 0u, entry);
            if (old == 0u) return h;
            cur = old;
        }
        if ((cur >> 16) == key) {          // same cell: max prio wins (hi bits equal)
            atomicMax(&table[h], entry);
            return h;
        }
        h = (h + 1) & (TS - 1);
    }
}

__global__ __launch_bounds__(THREADS, 4)
void bond_weight_kernel(const float* __restrict__ weights,
                        const int*   __restrict__ bond_src,
                        const int*   __restrict__ bond_dst,
                        const int*   __restrict__ bond_type,
                        float*       __restrict__ out)
{
    __shared__ uint32_t table[TS];          // key|prio (8 KB)
    __shared__ uint32_t bitmap[NWORDS];     // occupied cells (8 KB)
    __shared__ uint16_t rankw[NWORDS];      // exclusive prefix popcount per word (4 KB)
    __shared__ float    cvals[2 * E];       // compact winner values, cell-id order (4 KB)
    __shared__ uint32_t warpsum[16];

    const int t = threadIdx.x;
    const int      wsub  = t >> 3;            // word sub-index (8 float4 per word)
    const uint32_t sh    = (t & 7u) * 4u;     // loop-invariant nibble shift
    const uint32_t below = (1u << sh) - 1u;
    const float4   z = make_float4(0.f, 0.f, 0.f, 0.f);

    #pragma unroll 1
    for (int sub = 0; sub < BATCHES_PER_BLOCK; sub++) {
        const int b = blockIdx.x * BATCHES_PER_BLOCK + sub;

        // ---- edge loads FIRST: global latency overlaps the smem clears ----
        const int eidx = b * E + t;                // 512 threads == 512 edges
        const int sv = bond_src[eidx];
        const int dv = bond_dst[eidx];
        const int tv = bond_type[eidx];

        // previous iteration's hot loop reads smem -> fence before re-clearing
        __syncthreads();

        // ---- clear hash + bitmap ----
        #pragma unroll
        for (int i = 0; i < NWORDS / THREADS; i++) {
            table [t + i * THREADS] = 0u;
            bitmap[t + i * THREADS] = 0u;
        }

        const int   s = sv + 1;                    // 1..255
        const int   d = dv + 1;
        const float w = weights[tv];

        const uint32_t key1  = (uint32_t)(s * Nn + d); // pass 0: [src,dst]
        const uint32_t key2  = (uint32_t)(d * Nn + s); // pass 1: [dst,src]
        const uint32_t prio1 = (uint32_t)(t + 1);      // ref: pass0 e=0..E-1, then pass1;
        const uint32_t prio2 = (uint32_t)(E + t + 1);  // later application wins

        __syncthreads();   // clears visible

        const uint32_t slot1 = ht_insert(table, key1, prio1);
        const uint32_t slot2 = ht_insert(table, key2, prio2);
        atomicOr(&bitmap[key1 >> 5], 1u << (key1 & 31));
        atomicOr(&bitmap[key2 >> 5], 1u << (key2 & 31));

        __syncthreads();   // inserts + bitmap final

        // ---- block-wide exclusive prefix sum of per-word popcounts ----
        {
            const int base4 = t * 4;               // 512 threads x 4 words = 2048
            const uint32_t c0 = __popc(bitmap[base4 + 0]);
            const uint32_t c1 = __popc(bitmap[base4 + 1]);
            const uint32_t c2 = __popc(bitmap[base4 + 2]);
            const uint32_t c3 = __popc(bitmap[base4 + 3]);
            const uint32_t ssum = c0 + c1 + c2 + c3;

            const uint32_t lane = t & 31, wrp = t >> 5;
            uint32_t x = ssum;
            #pragma unroll
            for (int off = 1; off < 32; off <<= 1) {
                uint32_t y = __shfl_up_sync(0xFFFFFFFFu, x, off);
                if (lane >= off) x += y;
            }
            if (lane == 31) warpsum[wrp] = x;      // warp totals (inclusive)
            __syncthreads();
            if (t == 0) {                          // serial scan of 16 warp totals
                uint32_t acc = 0;
                #pragma unroll
                for (int i = 0; i < 16; i++) { uint32_t v = warpsum[i]; warpsum[i] = acc; acc += v; }
            }
            __syncthreads();
            const uint32_t excl = warpsum[wrp] + (x - ssum);   // thread-exclusive prefix
            rankw[base4 + 0] = (uint16_t)(excl);
            rankw[base4 + 1] = (uint16_t)(excl + c0);
            rankw[base4 + 2] = (uint16_t)(excl + c0 + c1);
            rankw[base4 + 3] = (uint16_t)(excl + c0 + c1 + c2);
        }
        __syncthreads();   // rank ready

        // ---- winners deposit values at their compact (cell-id-ordered) position ----
        {
            if ((table[slot1] & 0xFFFFu) == prio1) {
                uint32_t wd = key1 >> 5, bt = key1 & 31;
                uint32_t pos = (uint32_t)rankw[wd] + __popc(bitmap[wd] & ((1u << bt) - 1u));
                cvals[pos] = w;
            }
            if ((table[slot2] & 0xFFFFu) == prio2) {
                uint32_t wd = key2 >> 5, bt = key2 & 31;
                uint32_t pos = (uint32_t)rankw[wd] + __popc(bitmap[wd] & ((1u << bt) - 1u));
                cvals[pos] = w;
            }
        }
        __syncthreads();   // cvals ready

        // ---- single streaming pass over this batch's 256 KB slice ----
        float4* o4 = reinterpret_cast<float4*>(out + (size_t)b * CELLS);

        #pragma unroll
        for (int i = 0; i < ITERS; i++) {               // 32 float4 per thread
            const int idx = i * THREADS + t;            // coalesced float4 index
            const uint32_t word = bitmap[i * 64 + wsub];// LDS broadcast across 8 lanes
            const uint32_t nib  = (word >> sh) & 0xFu;
            float4 v = z;
            if (nib) {                                  // ~6% of nibbles; O(1)
                uint32_t p = (uint32_t)rankw[i * 64 + wsub] + __popc(word & below);
                if (nib & 1u) v.x = cvals[p++];
                if (nib & 2u) v.y = cvals[p++];
                if (nib & 4u) v.z = cvals[p++];
                if (nib & 8u) v.w = cvals[p];
            }
            __stcs(o4 + idx, v);    // streaming: each line written exactly once
        }
    }
}

extern "C" void kernel_launch(void* const* d_in, const int* in_sizes, int n_in,
                              void* d_out, int out_size)
{
    const float* weights   = (const float*)d_in[0];
    const int*   bond_src  = (const int*)  d_in[1];
    const int*   bond_dst  = (const int*)  d_in[2];
    const int*   bond_type = (const int*)  d_in[3];
    float* out = (float*)d_out;

    bond_weight_kernel<<<GRID, THREADS>>>(weights, bond_src, bond_dst, bond_type, out);
}

// round 14
// speedup vs baseline: 1.1332x; 1.1332x over previous
#include <cuda_runtime.h>
#include <stdint.h>

// weights[T=8] f32; bond_src/dst/type [B=1024,E=512] i32 (+1 node offset);
// out [B,256,256] f32 (256 MiB).
//
// Fused single-pass kernel (proven structure, 47.7us): one block per batch,
// smem hash dedup (reference last-write-wins order), bitmap + rank/popcount +
// compact values, ONE streaming pass writing every 128B line exactly once.
//
// R14 delta vs R12: pack the 3-bit bond type INTO the hash entry
// (key:16 | prio:11 | type:3). The atomicMax resolves winner AND weight type
// in one shot, so the winner-deposit phase becomes a uniform 4-slot sweep
// (no table re-reads, no divergent winner branches) -> shorter exposed
// prologue, especially for wave-2 CTAs. Grid stays 1024 (2 waves — measured
// faster than single-wave folding in R13).
static constexpr int Bb      = 1024;
static constexpr int E       = 512;
static constexpr int Nn      = 256;
static constexpr int CELLS   = Nn * Nn;     // 65536 cells / batch (256 KB)
static constexpr int NWORDS  = CELLS / 32;  // 2048 bitmap words
static constexpr int TS      = 2048;        // hash slots (<=0.5 load)
static constexpr int THREADS = 512;
static constexpr int ITERS   = (CELLS / 4) / THREADS;   // 32 float4 per thread

__device__ __forceinline__ uint32_t ht_hash(uint32_t key) {
    return (key * 2654435761u) >> (32 - 11);            // -> [0, 2048)
}

// Entry layout: key[31:14] (16b used) | prio[13:3] (11b, 1..1024) | type[2:0].
// key >= 257 so a valid entry is never 0. Same-key atomicMax compares prio
// first (type bits are below prio, and prios are unique per edge-pass).
__device__ __forceinline__ void ht_insert(uint32_t* table, uint32_t key, uint32_t prio,
                                          uint32_t typ) {
    uint32_t entry = (key << 14) | (prio << 3) | typ;
    uint32_t h = ht_hash(key);
    #pragma unroll 1
    while (true) {
        uint32_t cur = table[h];
        if (cur == 0u) {
            uint32_t old = atomicCAS(&table[h], 0u, entry);
            if (old == 0u) return;
            cur = old;
        }
        if ((cur >> 14) == key) {          // same cell: max prio wins
            atomicMax(&table[h], entry);
            return;
        }
        h = (h + 1) & (TS - 1);
    }
}

__global__ __launch_bounds__(THREADS, 4)
void bond_weight_kernel(const float* __restrict__ weights,
                        const int*   __restrict__ bond_src,
                        const int*   __restrict__ bond_dst,
                        const int*   __restrict__ bond_type,
                        float*       __restrict__ out)
{
    __shared__ uint32_t table[TS];          // key|prio|type (8 KB)
    __shared__ uint32_t bitmap[NWORDS];     // occupied cells (8 KB)
    __shared__ uint16_t rankw[NWORDS];      // exclusive prefix popcount per word (4 KB)
    __shared__ float    cvals[2 * E];       // compact winner values, cell-id order (4 KB)
    __shared__ uint32_t warpsum[16];
    __shared__ float    wsh[8];             // the 8 bond-type weights

    const int b = blockIdx.x;
    const int t = threadIdx.x;

    // ---- edge loads FIRST: global latency overlaps the smem clears below ----
    const int eidx = b * E + t;                    // 512 threads == 512 edges
    const int sv = bond_src[eidx];
    const int dv = bond_dst[eidx];
    const int tv = bond_type[eidx];

    if (t < 8) wsh[t] = weights[t];

    // ---- clear hash + bitmap ----
    #pragma unroll
    for (int i = 0; i < NWORDS / THREADS; i++) {
        table [t + i * THREADS] = 0u;
        bitmap[t + i * THREADS] = 0u;
    }

    const int s = sv + 1;                          // 1..255
    const int d = dv + 1;

    const uint32_t key1  = (uint32_t)(s * Nn + d); // pass 0: [src,dst]
    const uint32_t key2  = (uint32_t)(d * Nn + s); // pass 1: [dst,src]
    const uint32_t prio1 = (uint32_t)(t + 1);      // ref: pass0 e=0..E-1, then pass1;
    const uint32_t prio2 = (uint32_t)(E + t + 1);  // later application wins
    const uint32_t typ   = (uint32_t)tv;           // 0..7

    __syncthreads();   // clears visible

    ht_insert(table, key1, prio1, typ);
    ht_insert(table, key2, prio2, typ);
    atomicOr(&bitmap[key1 >> 5], 1u << (key1 & 31));
    atomicOr(&bitmap[key2 >> 5], 1u << (key2 & 31));

    __syncthreads();   // inserts + bitmap final

    // ---- block-wide exclusive prefix sum of per-word popcounts ----
    {
        const int base4 = t * 4;                   // 512 threads x 4 words = 2048
        const uint32_t c0 = __popc(bitmap[base4 + 0]);
        const uint32_t c1 = __popc(bitmap[base4 + 1]);
        const uint32_t c2 = __popc(bitmap[base4 + 2]);
        const uint32_t c3 = __popc(bitmap[base4 + 3]);
        const uint32_t ssum = c0 + c1 + c2 + c3;

        const uint32_t lane = t & 31, wrp = t >> 5;
        uint32_t x = ssum;
        #pragma unroll
        for (int off = 1; off < 32; off <<= 1) {
            uint32_t y = __shfl_up_sync(0xFFFFFFFFu, x, off);
            if (lane >= off) x += y;
        }
        if (lane == 31) warpsum[wrp] = x;          // warp totals (inclusive)
        __syncthreads();
        if (t == 0) {                              // serial scan of 16 warp totals
            uint32_t acc = 0;
            #pragma unroll
            for (int i = 0; i < 16; i++) { uint32_t v = warpsum[i]; warpsum[i] = acc; acc += v; }
        }
        __syncthreads();
        const uint32_t excl = warpsum[wrp] + (x - ssum);   // thread-exclusive prefix
        rankw[base4 + 0] = (uint16_t)(excl);
        rankw[base4 + 1] = (uint16_t)(excl + c0);
        rankw[base4 + 2] = (uint16_t)(excl + c0 + c1);
        rankw[base4 + 3] = (uint16_t)(excl + c0 + c1 + c2);
    }
    __syncthreads();   // rank ready

    // ---- uniform table sweep: every occupied slot emits its winning value ----
    // (winner + type already resolved inside the entry by atomicMax)
    #pragma unroll
    for (int i = 0; i < TS / THREADS; i++) {       // 4 slots per thread
        const uint32_t e = table[t + i * THREADS];
        if (e) {
            const uint32_t key = e >> 14;
            const uint32_t wd = key >> 5, bt = key & 31;
            const uint32_t pos = (uint32_t)rankw[wd]
                               + __popc(bitmap[wd] & ((1u << bt) - 1u));
            cvals[pos] = wsh[e & 7u];
        }
    }
    __syncthreads();   // cvals ready

    // ---- single streaming pass over the 256 KB slice (O(1) rare-path) ----
    float4* o4 = reinterpret_cast<float4*>(out + (size_t)b * CELLS);
    const float4 z = make_float4(0.f, 0.f, 0.f, 0.f);
    const int      wsub  = t >> 3;            // word sub-index (8 float4 per word)
    const uint32_t sh    = (t & 7u) * 4u;     // loop-invariant nibble shift
    const uint32_t below = (1u << sh) - 1u;

    #pragma unroll
    for (int i = 0; i < ITERS; i++) {                   // 32 float4 per thread
        const int idx = i * THREADS + t;                // coalesced float4 index
        const uint32_t word = bitmap[i * 64 + wsub];    // LDS broadcast across 8 lanes
        const uint32_t nib  = (word >> sh) & 0xFu;
        float4 v = z;
        if (nib) {                                      // ~6% of nibbles; O(1)
            uint32_t p = (uint32_t)rankw[i * 64 + wsub] + __popc(word & below);
            if (nib & 1u) v.x = cvals[p++];
            if (nib & 2u) v.y = cvals[p++];
            if (nib & 4u) v.z = cvals[p++];
            if (nib & 8u) v.w = cvals[p];
        }
        __stcs(o4 + idx, v);    // streaming store: each line written exactly once
    }
}

extern "C" void kernel_launch(void* const* d_in, const int* in_sizes, int n_in,
                              void* d_out, int out_size)
{
    const float* weights   = (const float*)d_in[0];
    const int*   bond_src  = (const int*)  d_in[1];
    const int*   bond_dst  = (const int*)  d_in[2];
    const int*   bond_type = (const int*)  d_in[3];
    float* out = (float*)d_out;

    bond_weight_kernel<<<Bb, THREADS>>>(weights, bond_src, bond_dst, bond_type, out);
}

// round 15
// speedup vs baseline: 1.1339x; 1.0007x over previous
#include <cuda_runtime.h>
#include <stdint.h>

// weights[T=8] f32; bond_src/dst/type [B=1024,E=512] i32 (+1 node offset);
// out [B,256,256] f32 (256 MiB).
//
// FINAL (best measured: 47.68us bench / 47.90us ncu, rel_err 0.0).
// Fused single-pass kernel: one block per batch,
//   - smem hash dedup (reference last-write-wins order via packed key|prio),
//   - occupancy bitmap + rank (prefix popcounts) + compact value array,
//   - ONE streaming pass writing every 128B output line exactly once.
//
// Bottleneck analysis (14 rounds): duration == LTS double-touch of the full
// 256MB output (store-allocate + dirty-evict = 524MB @ ~11TB/s LTS cap) with
// the ~4.5TB/s DRAM write drain co-binding. Falsified levers: store width,
// store/evict policy, L2 residency hints (carveout unavailable under harness
// rules), single-wave grid folding, prologue uniformity. This is the floor.
static constexpr int Bb      = 1024;
static constexpr int E       = 512;
static constexpr int Nn      = 256;
static constexpr int CELLS   = Nn * Nn;     // 65536 cells / batch (256 KB)
static constexpr int NWORDS  = CELLS / 32;  // 2048 bitmap words
static constexpr int TS      = 2048;        // hash slots (<=0.5 load)
static constexpr int THREADS = 512;
static constexpr int ITERS   = (CELLS / 4) / THREADS;   // 32 float4 per thread

__device__ __forceinline__ uint32_t ht_hash(uint32_t key) {
    return (key * 2654435761u) >> (32 - 11);            // -> [0, 2048)
}

// Entry: key(16b hi) | prio(16b lo). key in [257,65535] so entry!=0 when valid.
// Returns the slot where `key` resides.
__device__ __forceinline__ uint32_t ht_insert(uint32_t* table, uint32_t key, uint32_t prio) {
    uint32_t entry = (key << 16) | prio;
    uint32_t h = ht_hash(key);
    #pragma unroll 1
    while (true) {
        uint32_t cur = table[h];
        if (cur == 0u) {
            uint32_t old = atomicCAS(&table[h], 0u, entry);
            if (old == 0u) return h;
            cur = old;
        }
        if ((cur >> 16) == key) {          // same cell: max prio wins (hi bits equal)
            atomicMax(&table[h], entry);
            return h;
        }
        h = (h + 1) & (TS - 1);
    }
}

__global__ __launch_bounds__(THREADS, 4)
void bond_weight_kernel(const float* __restrict__ weights,
                        const int*   __restrict__ bond_src,
                        const int*   __restrict__ bond_dst,
                        const int*   __restrict__ bond_type,
                        float*       __restrict__ out)
{
    __shared__ uint32_t table[TS];          // key|prio (8 KB)
    __shared__ uint32_t bitmap[NWORDS];     // occupied cells (8 KB)
    __shared__ uint16_t rankw[NWORDS];      // exclusive prefix popcount per word (4 KB)
    __shared__ float    cvals[2 * E];       // compact winner values, cell-id order (4 KB)
    __shared__ uint32_t warpsum[16];

    const int b = blockIdx.x;
    const int t = threadIdx.x;

    // ---- edge loads FIRST: global latency overlaps the smem clears below ----
    const int eidx = b * E + t;                    // 512 threads == 512 edges
    const int sv = bond_src[eidx];
    const int dv = bond_dst[eidx];
    const int tv = bond_type[eidx];

    // ---- clear hash + bitmap ----
    #pragma unroll
    for (int i = 0; i < NWORDS / THREADS; i++) {
        table [t + i * THREADS] = 0u;
        bitmap[t + i * THREADS] = 0u;
    }

    const int   s = sv + 1;                        // 1..255
    const int   d = dv + 1;
    const float w = weights[tv];

    const uint32_t key1  = (uint32_t)(s * Nn + d); // pass 0: [src,dst]
    const uint32_t key2  = (uint32_t)(d * Nn + s); // pass 1: [dst,src]
    const uint32_t prio1 = (uint32_t)(t + 1);      // ref: pass0 e=0..E-1, then pass1;
    const uint32_t prio2 = (uint32_t)(E + t + 1);  // later application wins

    __syncthreads();   // clears visible

    const uint32_t slot1 = ht_insert(table, key1, prio1);
    const uint32_t slot2 = ht_insert(table, key2, prio2);
    atomicOr(&bitmap[key1 >> 5], 1u << (key1 & 31));
    atomicOr(&bitmap[key2 >> 5], 1u << (key2 & 31));

    __syncthreads();   // inserts + bitmap final

    // ---- block-wide exclusive prefix sum of per-word popcounts ----
    {
        const int base4 = t * 4;                   // 512 threads x 4 words = 2048
        const uint32_t c0 = __popc(bitmap[base4 + 0]);
        const uint32_t c1 = __popc(bitmap[base4 + 1]);
        const uint32_t c2 = __popc(bitmap[base4 + 2]);
        const uint32_t c3 = __popc(bitmap[base4 + 3]);
        const uint32_t ssum = c0 + c1 + c2 + c3;

        const uint32_t lane = t & 31, wrp = t >> 5;
        uint32_t x = ssum;
        #pragma unroll
        for (int off = 1; off < 32; off <<= 1) {
            uint32_t y = __shfl_up_sync(0xFFFFFFFFu, x, off);
            if (lane >= off) x += y;
        }
        if (lane == 31) warpsum[wrp] = x;          // warp totals (inclusive)
        __syncthreads();
        if (t == 0) {                              // serial scan of 16 warp totals
            uint32_t acc = 0;
            #pragma unroll
            for (int i = 0; i < 16; i++) { uint32_t v = warpsum[i]; warpsum[i] = acc; acc += v; }
        }
        __syncthreads();
        const uint32_t excl = warpsum[wrp] + (x - ssum);   // thread-exclusive prefix
        rankw[base4 + 0] = (uint16_t)(excl);
        rankw[base4 + 1] = (uint16_t)(excl + c0);
        rankw[base4 + 2] = (uint16_t)(excl + c0 + c1);
        rankw[base4 + 3] = (uint16_t)(excl + c0 + c1 + c2);
    }
    __syncthreads();   // rank ready

    // ---- winners deposit values at their compact (cell-id-ordered) position ----
    {
        if ((table[slot1] & 0xFFFFu) == prio1) {
            uint32_t wd = key1 >> 5, bt = key1 & 31;
            uint32_t pos = (uint32_t)rankw[wd] + __popc(bitmap[wd] & ((1u << bt) - 1u));
            cvals[pos] = w;
        }
        if ((table[slot2] & 0xFFFFu) == prio2) {
            uint32_t wd = key2 >> 5, bt = key2 & 31;
            uint32_t pos = (uint32_t)rankw[wd] + __popc(bitmap[wd] & ((1u << bt) - 1u));
            cvals[pos] = w;
        }
    }
    __syncthreads();   // cvals ready

    // ---- single streaming pass over the 256 KB slice (O(1) rare-path) ----
    float4* o4 = reinterpret_cast<float4*>(out + (size_t)b * CELLS);
    const float4 z = make_float4(0.f, 0.f, 0.f, 0.f);
    const int      wsub  = t >> 3;            // word sub-index (8 float4 per word)
    const uint32_t sh    = (t & 7u) * 4u;     // loop-invariant nibble shift
    const uint32_t below = (1u << sh) - 1u;

    #pragma unroll
    for (int i = 0; i < ITERS; i++) {                   // 32 float4 per thread
        const int idx = i * THREADS + t;                // coalesced float4 index
        const uint32_t word = bitmap[i * 64 + wsub];    // LDS broadcast across 8 lanes
        const uint32_t nib  = (word >> sh) & 0xFu;
        float4 v = z;
        if (nib) {                                      // ~6% of nibbles; O(1)
            uint32_t p = (uint32_t)rankw[i * 64 + wsub] + __popc(word & below);
            if (nib & 1u) v.x = cvals[p++];
            if (nib & 2u) v.y = cvals[p++];
            if (nib & 4u) v.z = cvals[p++];
            if (nib & 8u) v.w = cvals[p];
        }
        __stcs(o4 + idx, v);    // streaming store: each line written exactly once
    }
}

extern "C" void kernel_launch(void* const* d_in, const int* in_sizes, int n_in,
                              void* d_out, int out_size)
{
    const float* weights   = (const float*)d_in[0];
    const int*   bond_src  = (const int*)  d_in[1];
    const int*   bond_dst  = (const int*)  d_in[2];
    const int*   bond_type = (const int*)  d_in[3];
    float* out = (float*)d_out;

    bond_weight_kernel<<<Bb, THREADS>>>(weights, bond_src, bond_dst, bond_type, out);
}

// round 16
// speedup vs baseline: 1.1376x; 1.0033x over previous
#include <cuda_runtime.h>
#include <stdint.h>

// weights[T=8] f32; bond_src/dst/type [B=1024,E=512] i32 (+1 node offset);
// out [B,256,256] f32 (256 MiB).
//
// FINAL (best measured: 47.46us ncu / 47.68us bench, rel_err 0.0).
// Fused single-pass kernel: one block per batch,
//   - smem hash dedup (reference last-write-wins order via packed key|prio),
//   - occupancy bitmap + rank (prefix popcounts) + compact value array,
//   - ONE streaming pass writing every 128B output line exactly once.
//
// Bottleneck (15 rounds, converged): full 256MB output must be rewritten each
// launch; duration == DRAM write drain (~215MB @ ~4.5TB/s effective HBM write
// ceiling) with LTS store-allocate traffic co-binding. Falsified levers:
// store width (v8 regressed), evict policy (neutral), L2 residency hints
// (carveout unavailable under harness rules), single-wave folding (regressed),
// prologue uniformity (neutral). This is the structural floor.
static constexpr int Bb      = 1024;
static constexpr int E       = 512;
static constexpr int Nn      = 256;
static constexpr int CELLS   = Nn * Nn;     // 65536 cells / batch (256 KB)
static constexpr int NWORDS  = CELLS / 32;  // 2048 bitmap words
static constexpr int TS      = 2048;        // hash slots (<=0.5 load)
static constexpr int THREADS = 512;
static constexpr int ITERS   = (CELLS / 4) / THREADS;   // 32 float4 per thread

__device__ __forceinline__ uint32_t ht_hash(uint32_t key) {
    return (key * 2654435761u) >> (32 - 11);            // -> [0, 2048)
}

// Entry: key(16b hi) | prio(16b lo). key in [257,65535] so entry!=0 when valid.
// Returns the slot where `key` resides.
__device__ __forceinline__ uint32_t ht_insert(uint32_t* table, uint32_t key, uint32_t prio) {
    uint32_t entry = (key << 16) | prio;
    uint32_t h = ht_hash(key);
    #pragma unroll 1
    while (true) {
        uint32_t cur = table[h];
        if (cur == 0u) {
            uint32_t old = atomicCAS(&table[h], 0u, entry);
            if (old == 0u) return h;
            cur = old;
        }
        if ((cur >> 16) == key) {          // same cell: max prio wins (hi bits equal)
            atomicMax(&table[h], entry);
            return h;
        }
        h = (h + 1) & (TS - 1);
    }
}

__global__ __launch_bounds__(THREADS, 4)
void bond_weight_kernel(const float* __restrict__ weights,
                        const int*   __restrict__ bond_src,
                        const int*   __restrict__ bond_dst,
                        const int*   __restrict__ bond_type,
                        float*       __restrict__ out)
{
    __shared__ uint32_t table[TS];          // key|prio (8 KB)
    __shared__ uint32_t bitmap[NWORDS];     // occupied cells (8 KB)
    __shared__ uint16_t rankw[NWORDS];      // exclusive prefix popcount per word (4 KB)
    __shared__ float    cvals[2 * E];       // compact winner values, cell-id order (4 KB)
    __shared__ uint32_t warpsum[16];

    const int b = blockIdx.x;
    const int t = threadIdx.x;

    // ---- edge loads FIRST: global latency overlaps the smem clears below ----
    const int eidx = b * E + t;                    // 512 threads == 512 edges
    const int sv = bond_src[eidx];
    const int dv = bond_dst[eidx];
    const int tv = bond_type[eidx];

    // ---- clear hash + bitmap ----
    #pragma unroll
    for (int i = 0; i < NWORDS / THREADS; i++) {
        table [t + i * THREADS] = 0u;
        bitmap[t + i * THREADS] = 0u;
    }

    const int   s = sv + 1;                        // 1..255
    const int   d = dv + 1;
    const float w = weights[tv];

    const uint32_t key1  = (uint32_t)(s * Nn + d); // pass 0: [src,dst]
    const uint32_t key2  = (uint32_t)(d * Nn + s); // pass 1: [dst,src]
    const uint32_t prio1 = (uint32_t)(t + 1);      // ref: pass0 e=0..E-1, then pass1;
    const uint32_t prio2 = (uint32_t)(E + t + 1);  // later application wins

    __syncthreads();   // clears visible

    const uint32_t slot1 = ht_insert(table, key1, prio1);
    const uint32_t slot2 = ht_insert(table, key2, prio2);
    atomicOr(&bitmap[key1 >> 5], 1u << (key1 & 31));
    atomicOr(&bitmap[key2 >> 5], 1u << (key2 & 31));

    __syncthreads();   // inserts + bitmap final

    // ---- block-wide exclusive prefix sum of per-word popcounts ----
    {
        const int base4 = t * 4;                   // 512 threads x 4 words = 2048
        const uint32_t c0 = __popc(bitmap[base4 + 0]);
        const uint32_t c1 = __popc(bitmap[base4 + 1]);
        const uint32_t c2 = __popc(bitmap[base4 + 2]);
        const uint32_t c3 = __popc(bitmap[base4 + 3]);
        const uint32_t ssum = c0 + c1 + c2 + c3;

        const uint32_t lane = t & 31, wrp = t >> 5;
        uint32_t x = ssum;
        #pragma unroll
        for (int off = 1; off < 32; off <<= 1) {
            uint32_t y = __shfl_up_sync(0xFFFFFFFFu, x, off);
            if (lane >= off) x += y;
        }
        if (lane == 31) warpsum[wrp] = x;          // warp totals (inclusive)
        __syncthreads();
        if (t == 0) {                              // serial scan of 16 warp totals
            uint32_t acc = 0;
            #pragma unroll
            for (int i = 0; i < 16; i++) { uint32_t v = warpsum[i]; warpsum[i] = acc; acc += v; }
        }
        __syncthreads();
        const uint32_t excl = warpsum[wrp] + (x - ssum);   // thread-exclusive prefix
        rankw[base4 + 0] = (uint16_t)(excl);
        rankw[base4 + 1] = (uint16_t)(excl + c0);
        rankw[base4 + 2] = (uint16_t)(excl + c0 + c1);
        rankw[base4 + 3] = (uint16_t)(excl + c0 + c1 + c2);
    }
    __syncthreads();   // rank ready

    // ---- winners deposit values at their compact (cell-id-ordered) position ----
    {
        if ((table[slot1] & 0xFFFFu) == prio1) {
            uint32_t wd = key1 >> 5, bt = key1 & 31;
            uint32_t pos = (uint32_t)rankw[wd] + __popc(bitmap[wd] & ((1u << bt) - 1u));
            cvals[pos] = w;
        }
        if ((table[slot2] & 0xFFFFu) == prio2) {
            uint32_t wd = key2 >> 5, bt = key2 & 31;
            uint32_t pos = (uint32_t)rankw[wd] + __popc(bitmap[wd] & ((1u << bt) - 1u));
            cvals[pos] = w;
        }
    }
    __syncthreads();   // cvals ready

    // ---- single streaming pass over the 256 KB slice (O(1) rare-path) ----
    float4* o4 = reinterpret_cast<float4*>(out + (size_t)b * CELLS);
    const float4 z = make_float4(0.f, 0.f, 0.f, 0.f);
    const int      wsub  = t >> 3;            // word sub-index (8 float4 per word)
    const uint32_t sh    = (t & 7u) * 4u;     // loop-invariant nibble shift
    const uint32_t below = (1u << sh) - 1u;

    #pragma unroll
    for (int i = 0; i < ITERS; i++) {                   // 32 float4 per thread
        const int idx = i * THREADS + t;                // coalesced float4 index
        const uint32_t word = bitmap[i * 64 + wsub];    // LDS broadcast across 8 lanes
        const uint32_t nib  = (word >> sh) & 0xFu;
        float4 v = z;
        if (nib) {                                      // ~6% of nibbles; O(1)
            uint32_t p = (uint32_t)rankw[i * 64 + wsub] + __popc(word & below);
            if (nib & 1u) v.x = cvals[p++];
            if (nib & 2u) v.y = cvals[p++];
            if (nib & 4u) v.z = cvals[p++];
            if (nib & 8u) v.w = cvals[p];
        }
        __stcs(o4 + idx, v);    // streaming store: each line written exactly once
    }
}

extern "C" void kernel_launch(void* const* d_in, const int* in_sizes, int n_in,
                              void* d_out, int out_size)
{
    const float* weights   = (const float*)d_in[0];
    const int*   bond_src  = (const int*)  d_in[1];
    const int*   bond_dst  = (const int*)  d_in[2];
    const int*   bond_type = (const int*)  d_in[3];
    float* out = (float*)d_out;

    bond_weight_kernel<<<Bb, THREADS>>>(weights, bond_src, bond_dst, bond_type, out);
}

// round 17
// speedup vs baseline: 1.1421x; 1.0039x over previous
#include <cuda_runtime.h>
#include <stdint.h>

// weights[T=8] f32; bond_src/dst/type [B=1024,E=512] i32 (+1 node offset);
// out [B,256,256] f32 (256 MiB).
//
// FINAL (best measured: 47.46us ncu / 47.68us bench, rel_err 0.0; stable
// across 4 independent runs at 47.5-47.9us kernel time).
// Fused single-pass kernel: one block per batch,
//   - smem hash dedup (reference last-write-wins order via packed key|prio),
//   - occupancy bitmap + rank (prefix popcounts) + compact value array,
//   - ONE streaming pass writing every 128B output line exactly once.
//
// Bottleneck (16 rounds, converged): full 256MB output must be rewritten each
// launch (harness poisons d_out); duration == DRAM write drain (~215MB @
// ~4.5TB/s effective HBM write ceiling) with LTS store-allocate traffic
// co-binding. Falsified levers: store width (v8 regressed), evict policy
// (neutral), L2 residency hints (carveout unavailable under harness rules),
// single-wave grid folding (regressed), prologue uniformity (neutral),
// instruction-count reduction (R6: issue 10% ran SLOWER). Structural floor.
static constexpr int Bb      = 1024;
static constexpr int E       = 512;
static constexpr int Nn      = 256;
static constexpr int CELLS   = Nn * Nn;     // 65536 cells / batch (256 KB)
static constexpr int NWORDS  = CELLS / 32;  // 2048 bitmap words
static constexpr int TS      = 2048;        // hash slots (<=0.5 load)
static constexpr int THREADS = 512;
static constexpr int ITERS   = (CELLS / 4) / THREADS;   // 32 float4 per thread

__device__ __forceinline__ uint32_t ht_hash(uint32_t key) {
    return (key * 2654435761u) >> (32 - 11);            // -> [0, 2048)
}

// Entry: key(16b hi) | prio(16b lo). key in [257,65535] so entry!=0 when valid.
// Returns the slot where `key` resides.
__device__ __forceinline__ uint32_t ht_insert(uint32_t* table, uint32_t key, uint32_t prio) {
    uint32_t entry = (key << 16) | prio;
    uint32_t h = ht_hash(key);
    #pragma unroll 1
    while (true) {
        uint32_t cur = table[h];
        if (cur == 0u) {
            uint32_t old = atomicCAS(&table[h], 0u, entry);
            if (old == 0u) return h;
            cur = old;
        }
        if ((cur >> 16) == key) {          // same cell: max prio wins (hi bits equal)
            atomicMax(&table[h], entry);
            return h;
        }
        h = (h + 1) & (TS - 1);
    }
}

__global__ __launch_bounds__(THREADS, 4)
void bond_weight_kernel(const float* __restrict__ weights,
                        const int*   __restrict__ bond_src,
                        const int*   __restrict__ bond_dst,
                        const int*   __restrict__ bond_type,
                        float*       __restrict__ out)
{
    __shared__ uint32_t table[TS];          // key|prio (8 KB)
    __shared__ uint32_t bitmap[NWORDS];     // occupied cells (8 KB)
    __shared__ uint16_t rankw[NWORDS];      // exclusive prefix popcount per word (4 KB)
    __shared__ float    cvals[2 * E];       // compact winner values, cell-id order (4 KB)
    __shared__ uint32_t warpsum[16];

    const int b = blockIdx.x;
    const int t = threadIdx.x;

    // ---- edge loads FIRST: global latency overlaps the smem clears below ----
    const int eidx = b * E + t;                    // 512 threads == 512 edges
    const int sv = bond_src[eidx];
    const int dv = bond_dst[eidx];
    const int tv = bond_type[eidx];

    // ---- clear hash + bitmap ----
    #pragma unroll
    for (int i = 0; i < NWORDS / THREADS; i++) {
        table [t + i * THREADS] = 0u;
        bitmap[t + i * THREADS] = 0u;
    }

    const int   s = sv + 1;                        // 1..255
    const int   d = dv + 1;
    const float w = weights[tv];

    const uint32_t key1  = (uint32_t)(s * Nn + d); // pass 0: [src,dst]
    const uint32_t key2  = (uint32_t)(d * Nn + s); // pass 1: [dst,src]
    const uint32_t prio1 = (uint32_t)(t + 1);      // ref: pass0 e=0..E-1, then pass1;
    const uint32_t prio2 = (uint32_t)(E + t + 1);  // later application wins

    __syncthreads();   // clears visible

    const uint32_t slot1 = ht_insert(table, key1, prio1);
    const uint32_t slot2 = ht_insert(table, key2, prio2);
    atomicOr(&bitmap[key1 >> 5], 1u << (key1 & 31));
    atomicOr(&bitmap[key2 >> 5], 1u << (key2 & 31));

    __syncthreads();   // inserts + bitmap final

    // ---- block-wide exclusive prefix sum of per-word popcounts ----
    {
        const int base4 = t * 4;                   // 512 threads x 4 words = 2048
        const uint32_t c0 = __popc(bitmap[base4 + 0]);
        const uint32_t c1 = __popc(bitmap[base4 + 1]);
        const uint32_t c2 = __popc(bitmap[base4 + 2]);
        const uint32_t c3 = __popc(bitmap[base4 + 3]);
        const uint32_t ssum = c0 + c1 + c2 + c3;

        const uint32_t lane = t & 31, wrp = t >> 5;
        uint32_t x = ssum;
        #pragma unroll
        for (int off = 1; off < 32; off <<= 1) {
            uint32_t y = __shfl_up_sync(0xFFFFFFFFu, x, off);
            if (lane >= off) x += y;
        }
        if (lane == 31) warpsum[wrp] = x;          // warp totals (inclusive)
        __syncthreads();
        if (t == 0) {                              // serial scan of 16 warp totals
            uint32_t acc = 0;
            #pragma unroll
            for (int i = 0; i < 16; i++) { uint32_t v = warpsum[i]; warpsum[i] = acc; acc += v; }
        }
        __syncthreads();
        const uint32_t excl = warpsum[wrp] + (x - ssum);   // thread-exclusive prefix
        rankw[base4 + 0] = (uint16_t)(excl);
        rankw[base4 + 1] = (uint16_t)(excl + c0);
        rankw[base4 + 2] = (uint16_t)(excl + c0 + c1);
        rankw[base4 + 3] = (uint16_t)(excl + c0 + c1 + c2);
    }
    __syncthreads();   // rank ready

    // ---- winners deposit values at their compact (cell-id-ordered) position ----
    {
        if ((table[slot1] & 0xFFFFu) == prio1) {
            uint32_t wd = key1 >> 5, bt = key1 & 31;
            uint32_t pos = (uint32_t)rankw[wd] + __popc(bitmap[wd] & ((1u << bt) - 1u));
            cvals[pos] = w;
        }
        if ((table[slot2] & 0xFFFFu) == prio2) {
            uint32_t wd = key2 >> 5, bt = key2 & 31;
            uint32_t pos = (uint32_t)rankw[wd] + __popc(bitmap[wd] & ((1u << bt) - 1u));
            cvals[pos] = w;
        }
    }
    __syncthreads();   // cvals ready

    // ---- single streaming pass over the 256 KB slice (O(1) rare-path) ----
    float4* o4 = reinterpret_cast<float4*>(out + (size_t)b * CELLS);
    const float4 z = make_float4(0.f, 0.f, 0.f, 0.f);
    const int      wsub  = t >> 3;            // word sub-index (8 float4 per word)
    const uint32_t sh    = (t & 7u) * 4u;     // loop-invariant nibble shift
    const uint32_t below = (1u << sh) - 1u;

    #pragma unroll
    for (int i = 0; i < ITERS; i++) {                   // 32 float4 per thread
        const int idx = i * THREADS + t;                // coalesced float4 index
        const uint32_t word = bitmap[i * 64 + wsub];    // LDS broadcast across 8 lanes
        const uint32_t nib  = (word >> sh) & 0xFu;
        float4 v = z;
        if (nib) {                                      // ~6% of nibbles; O(1)
            uint32_t p = (uint32_t)rankw[i * 64 + wsub] + __popc(word & below);
            if (nib & 1u) v.x = cvals[p++];
            if (nib & 2u) v.y = cvals[p++];
            if (nib & 4u) v.z = cvals[p++];
            if (nib & 8u) v.w = cvals[p];
        }
        __stcs(o4 + idx, v);    // streaming store: each line written exactly once
    }
}

extern "C" void kernel_launch(void* const* d_in, const int* in_sizes, int n_in,
                              void* d_out, int out_size)
{
    const float* weights   = (const float*)d_in[0];
    const int*   bond_src  = (const int*)  d_in[1];
    const int*   bond_dst  = (const int*)  d_in[2];
    const int*   bond_type = (const int*)  d_in[3];
    float* out = (float*)d_out;

    bond_weight_kernel<<<Bb, THREADS>>>(weights, bond_src, bond_dst, bond_type, out);
}